// round 1
// baseline (speedup 1.0000x reference)
#include <cuda_runtime.h>

#define FULL 0xffffffffu
#define NQ 10
#define QL 4
#define DM 512
#define NTOK (8*2048)

// Precomputed weight-gate matrices: W = RZw * RY, complex 2x2 per (layer, qubit).
// Layout: [l][q][8] = {w00r,w00i, w01r,w01i, w10r,w10i, w11r,w11i}
__device__ float g_W[QL * NQ * 8];

__global__ void prep_kernel(const float* __restrict__ weights) {
    int t = threadIdx.x;
    if (t < QL * NQ) {
        float ty = 0.5f * weights[t * 2 + 0];
        float tz = 0.5f * weights[t * 2 + 1];
        float sy, cy, sz, cz;
        sincosf(ty, &sy, &cy);
        sincosf(tz, &sz, &cz);
        float* w = &g_W[t * 8];
        // Row0: (cz - i sz) * [cy, -sy]
        w[0] =  cz * cy;  w[1] = -sz * cy;
        w[2] = -cz * sy;  w[3] =  sz * sy;
        // Row1: (cz + i sz) * [sy, cy]
        w[4] =  cz * sy;  w[5] =  sz * sy;
        w[6] =  cz * cy;  w[7] =  sz * cy;
    }
}

__device__ __forceinline__ void cmad(float& cr, float& ci,
                                     float ar, float ai, float br, float bi) {
    // (cr,ci) += (ar + i ai) * (br + i bi)
    cr = fmaf(ar, br, cr);
    cr = fmaf(-ai, bi, cr);
    ci = fmaf(ar, bi, ci);
    ci = fmaf(ai, br, ci);
}

__device__ __forceinline__ float warp_sum(float v) {
#pragma unroll
    for (int o = 16; o; o >>= 1) v += __shfl_xor_sync(FULL, v, o);
    return v;
}

__global__ __launch_bounds__(128) void qsim_kernel(
    const float* __restrict__ x,
    const float* __restrict__ in_W,
    const float* __restrict__ in_b,
    const float* __restrict__ gamma,
    const float* __restrict__ beta,
    const float* __restrict__ out_W,
    const float* __restrict__ out_b,
    float* __restrict__ out)
{
    const int lane  = threadIdx.x & 31;
    const int warp  = threadIdx.x >> 5;
    const int token = blockIdx.x * 4 + warp;
    const float* xr = x + (size_t)token * DM;

    // ---------------- Stage 1: h = tanh(x @ in_W^T + b), LayerNorm ----------
    float acc[NQ];
#pragma unroll
    for (int q = 0; q < NQ; q++) acc[q] = 0.f;
#pragma unroll
    for (int i = 0; i < DM / 32; i++) {
        float xv = xr[lane + 32 * i];
#pragma unroll
        for (int q = 0; q < NQ; q++)
            acc[q] = fmaf(xv, __ldg(&in_W[q * DM + lane + 32 * i]), acc[q]);
    }
#pragma unroll
    for (int q = 0; q < NQ; q++) acc[q] = warp_sum(acc[q]);

    float mu = 0.f;
#pragma unroll
    for (int q = 0; q < NQ; q++) {
        acc[q] = tanhf(acc[q] + __ldg(&in_b[q]));
        mu += acc[q];
    }
    mu *= 0.1f;
    float var = 0.f;
#pragma unroll
    for (int q = 0; q < NQ; q++) {
        float d = acc[q] - mu;
        var = fmaf(d, d, var);
    }
    var *= 0.1f;
    float rstd = rsqrtf(var + 1e-5f);

    float cx[NQ], sx[NQ];
#pragma unroll
    for (int q = 0; q < NQ; q++) {
        float feat = fmaf((acc[q] - mu) * rstd, __ldg(&gamma[q]), __ldg(&beta[q]));
        float half = 0.5f * feat;
        sincosf(half, &sx[q], &cx[q]);
    }

    // ---------------- Stage 2: 10-qubit statevector sim ---------------------
    // flat amp index = (lane << 5) | r ; qubit q <-> bit (9 - q)
    float ar[32], ai[32];
#pragma unroll
    for (int r = 0; r < 32; r++) { ar[r] = 0.f; ai[r] = 0.f; }
    if (lane == 0) ar[0] = 1.f;

#pragma unroll 1
    for (int l = 0; l < QL; l++) {
        // --- fused single-qubit gates: M = (RZw*RY) * (RZt*RX) per qubit ---
#pragma unroll
        for (int q = 0; q < NQ; q++) {
            const int b = 9 - q;
            float c = cx[q], s = sx[q];
            float cc = c * c, ss = s * s, sc = s * c;
            // A = RZt*RX: a00=(cc,-sc) a01=(-ss,-sc) a10=(ss,-sc) a11=(cc,sc)
            const float* w = &g_W[(l * NQ + q) * 8];
            float w00r = w[0], w00i = w[1], w01r = w[2], w01i = w[3];
            float w10r = w[4], w10i = w[5], w11r = w[6], w11i = w[7];

            float m00r = 0.f, m00i = 0.f, m01r = 0.f, m01i = 0.f;
            float m10r = 0.f, m10i = 0.f, m11r = 0.f, m11i = 0.f;
            // m00 = w00*a00 + w01*a10
            cmad(m00r, m00i, w00r, w00i, cc, -sc);
            cmad(m00r, m00i, w01r, w01i, ss, -sc);
            // m01 = w00*a01 + w01*a11
            cmad(m01r, m01i, w00r, w00i, -ss, -sc);
            cmad(m01r, m01i, w01r, w01i, cc, sc);
            // m10 = w10*a00 + w11*a10
            cmad(m10r, m10i, w10r, w10i, cc, -sc);
            cmad(m10r, m10i, w11r, w11i, ss, -sc);
            // m11 = w10*a01 + w11*a11
            cmad(m11r, m11i, w10r, w10i, -ss, -sc);
            cmad(m11r, m11i, w11r, w11i, cc, sc);

            if (b >= 5) {
                // lane-bit gate via shuffle
                const int lb = b - 5;
                int v = (lane >> lb) & 1;
                float maar = v ? m11r : m00r, maai = v ? m11i : m00i;
                float mabr = v ? m10r : m01r, mabi = v ? m10i : m01i;
#pragma unroll
                for (int r = 0; r < 32; r++) {
                    float otr = __shfl_xor_sync(FULL, ar[r], 1 << lb);
                    float oti = __shfl_xor_sync(FULL, ai[r], 1 << lb);
                    float nr = maar * ar[r];
                    nr = fmaf(-maai, ai[r], nr);
                    nr = fmaf(mabr, otr, nr);
                    nr = fmaf(-mabi, oti, nr);
                    float ni = maar * ai[r];
                    ni = fmaf(maai, ar[r], ni);
                    ni = fmaf(mabr, oti, ni);
                    ni = fmaf(mabi, otr, ni);
                    ar[r] = nr; ai[r] = ni;
                }
            } else {
                // register-bit gate
                const int tb = 1 << b;
#pragma unroll
                for (int r = 0; r < 32; r++) {
                    if (r & tb) continue;
                    const int r2 = r | tb;
                    float a0r = ar[r], a0i = ai[r], a1r = ar[r2], a1i = ai[r2];
                    float n0r = 0.f, n0i = 0.f, n1r = 0.f, n1i = 0.f;
                    cmad(n0r, n0i, m00r, m00i, a0r, a0i);
                    cmad(n0r, n0i, m01r, m01i, a1r, a1i);
                    cmad(n1r, n1i, m10r, m10i, a0r, a0i);
                    cmad(n1r, n1i, m11r, m11i, a1r, a1i);
                    ar[r] = n0r; ai[r] = n0i; ar[r2] = n1r; ai[r2] = n1i;
                }
            }
        }

        // --- CNOT chain: (q, q+1 mod 10); control bit 9-q, target bit 9-((q+1)%10)
        // q=0..3: both lane bits
#pragma unroll
        for (int q = 0; q < 4; q++) {
            const int cmask = 1 << (4 - q);
            const int tmask = 1 << (3 - q);
            bool flip = (lane & cmask) != 0;
#pragma unroll
            for (int r = 0; r < 32; r++) {
                float tr = __shfl_xor_sync(FULL, ar[r], tmask);
                float ti = __shfl_xor_sync(FULL, ai[r], tmask);
                if (flip) { ar[r] = tr; ai[r] = ti; }
            }
        }
        // q=4: control lane bit 0, target reg bit 4
        {
            bool flip = (lane & 1) != 0;
#pragma unroll
            for (int r = 0; r < 16; r++) {
                const int r2 = r + 16;
                float tr = ar[r], ti = ai[r];
                ar[r]  = flip ? ar[r2] : ar[r];
                ai[r]  = flip ? ai[r2] : ai[r];
                ar[r2] = flip ? tr : ar[r2];
                ai[r2] = flip ? ti : ai[r2];
            }
        }
        // q=5..8: reg-reg (pure register permutation)
#pragma unroll
        for (int q = 5; q < 9; q++) {
            const int cb = 1 << (9 - q);
            const int tb = 1 << (8 - q);
#pragma unroll
            for (int r = 0; r < 32; r++) {
                if ((r & cb) && !(r & tb)) {
                    const int r2 = r | tb;
                    float tr = ar[r], ti = ai[r];
                    ar[r] = ar[r2]; ai[r] = ai[r2];
                    ar[r2] = tr;    ai[r2] = ti;
                }
            }
        }
        // q=9: control reg bit 0, target lane bit 4
        {
#pragma unroll
            for (int r = 1; r < 32; r += 2) {
                ar[r] = __shfl_xor_sync(FULL, ar[r], 16);
                ai[r] = __shfl_xor_sync(FULL, ai[r], 16);
            }
        }
    }

    // ---------------- Stage 3: measurement + output projection --------------
    float tot = 0.f, sb[5];
#pragma unroll
    for (int b = 0; b < 5; b++) sb[b] = 0.f;
#pragma unroll
    for (int r = 0; r < 32; r++) {
        float p = fmaf(ar[r], ar[r], ai[r] * ai[r]);
        tot += p;
#pragma unroll
        for (int b = 0; b < 5; b++)
            if (!((r >> b) & 1)) sb[b] += p;
    }

    float z[NQ];
    // reg-bit qubits: qubit 9-b uses reg bit b
#pragma unroll
    for (int b = 0; b < 5; b++) {
        float v = 2.f * sb[b] - tot;
        z[9 - b] = warp_sum(v);
    }
    // lane-bit qubits: qubit q (0..4) uses lane bit 4-q
#pragma unroll
    for (int q = 0; q < 5; q++) {
        const int lb = 4 - q;
        float v = ((lane >> lb) & 1) ? -tot : tot;
        z[q] = warp_sum(v);
    }

    float* outr = out + (size_t)token * DM;
#pragma unroll
    for (int i = 0; i < DM / 32; i++) {
        const int d = lane + 32 * i;
        float o = xr[d] + __ldg(&out_b[d]);
#pragma unroll
        for (int q = 0; q < NQ; q++)
            o = fmaf(z[q], __ldg(&out_W[d * NQ + q]), o);
        outr[d] = o;
    }
}

extern "C" void kernel_launch(void* const* d_in, const int* in_sizes, int n_in,
                              void* d_out, int out_size) {
    const float* x       = (const float*)d_in[0];
    const float* in_W    = (const float*)d_in[1];
    const float* in_b    = (const float*)d_in[2];
    const float* gamma   = (const float*)d_in[3];
    const float* beta    = (const float*)d_in[4];
    const float* weights = (const float*)d_in[5];
    const float* out_W   = (const float*)d_in[6];
    const float* out_b   = (const float*)d_in[7];
    float* out = (float*)d_out;

    prep_kernel<<<1, 64>>>(weights);
    qsim_kernel<<<NTOK / 4, 128>>>(x, in_W, in_b, gamma, beta, out_W, out_b, out);
}

// round 3
// speedup vs baseline: 1.6700x; 1.6700x over previous
#include <cuda_runtime.h>

typedef unsigned long long u64;
#define FULL 0xffffffffu
#define NQ 10
#define QL 4
#define DM 512
#define NTOK (8*2048)

// Precomputed weight-gate packs per (layer,qubit):
// [0..3] = W00,W01,W10,W11 as (re,im) packs
// [4] = i*W00 + i*W01, [5] = i*W01 - i*W00, [6] = i*W10 + i*W11, [7] = i*W11 - i*W10
__device__ u64 g_WP[QL * NQ * 8];

__device__ __forceinline__ u64 pk2(float lo, float hi) {
    u64 r; asm("mov.b64 %0,{%1,%2};" : "=l"(r) : "f"(lo), "f"(hi)); return r;
}
__device__ __forceinline__ void up2(u64 v, float& lo, float& hi) {
    asm("mov.b64 {%0,%1},%2;" : "=f"(lo), "=f"(hi) : "l"(v));
}
__device__ __forceinline__ u64 bc2(float v) { return pk2(v, v); }
__device__ __forceinline__ u64 ffma2(u64 a, u64 b, u64 c) {
    u64 d; asm("fma.rn.f32x2 %0,%1,%2,%3;" : "=l"(d) : "l"(a), "l"(b), "l"(c)); return d;
}
__device__ __forceinline__ u64 fmul2(u64 a, u64 b) {
    u64 d; asm("mul.rn.f32x2 %0,%1,%2;" : "=l"(d) : "l"(a), "l"(b)); return d;
}
__device__ __forceinline__ u64 fadd2(u64 a, u64 b) {
    u64 d; asm("add.rn.f32x2 %0,%1,%2;" : "=l"(d) : "l"(a), "l"(b)); return d;
}
__device__ __forceinline__ u64 swap2(u64 v) { float lo, hi; up2(v, lo, hi); return pk2(hi, lo); }

__global__ void prep_kernel(const float* __restrict__ weights) {
    int t = threadIdx.x;
    if (t < QL * NQ) {
        float ty = 0.5f * weights[t * 2 + 0];
        float tz = 0.5f * weights[t * 2 + 1];
        float sy, cy, sz, cz;
        sincosf(ty, &sy, &cy);
        sincosf(tz, &sz, &cz);
        // W = RZw * RY
        float w00r =  cz * cy, w00i = -sz * cy;
        float w01r = -cz * sy, w01i =  sz * sy;
        float w10r =  cz * sy, w10i =  sz * sy;
        float w11r =  cz * cy, w11i =  sz * cy;
        u64* o = &g_WP[t * 8];
        o[0] = pk2(w00r, w00i);
        o[1] = pk2(w01r, w01i);
        o[2] = pk2(w10r, w10i);
        o[3] = pk2(w11r, w11i);
        // i*w = (-wi, wr)
        o[4] = pk2(-w00i - w01i, w00r + w01r);   // S0 = iW00 + iW01
        o[5] = pk2( w00i - w01i, w01r - w00r);   // D0 = iW01 - iW00
        o[6] = pk2(-w10i - w11i, w10r + w11r);   // S1 = iW10 + iW11
        o[7] = pk2( w10i - w11i, w11r - w10r);   // D1 = iW11 - iW10
    }
}

__device__ __forceinline__ float warp_sum(float v) {
#pragma unroll
    for (int o = 16; o; o >>= 1) v += __shfl_xor_sync(FULL, v, o);
    return v;
}

// Fused gate matrix M = W * (RZt * RX), with A = RZt*RX:
// a00=(cc,-sc) a01=(-ss,-sc) a10=(ss,-sc) a11=(cc,sc)
__device__ __forceinline__ void build_m(int l, int q, float c, float s,
    float& m00r, float& m00i, float& m01r, float& m01i,
    float& m10r, float& m10i, float& m11r, float& m11i)
{
    const u64* w = &g_WP[(l * NQ + q) * 8];
    u64 W00 = w[0], W01 = w[1], W10 = w[2], W11 = w[3];
    u64 S0 = w[4], D0 = w[5], S1 = w[6], D1 = w[7];
    float cc = c * c, ss = s * s, sc = s * c;
    u64 CC = bc2(cc), SS = bc2(ss), NSS = bc2(-ss), SC = bc2(sc), NSC = bc2(-sc);
    u64 M00 = ffma2(SS, W01, ffma2(NSC, S0, fmul2(CC, W00)));
    u64 M01 = ffma2(NSS, W00, ffma2(SC, D0, fmul2(CC, W01)));
    u64 M10 = ffma2(SS, W11, ffma2(NSC, S1, fmul2(CC, W10)));
    u64 M11 = ffma2(NSS, W10, ffma2(SC, D1, fmul2(CC, W11)));
    up2(M00, m00r, m00i); up2(M01, m01r, m01i);
    up2(M10, m10r, m10i); up2(M11, m11r, m11i);
}

__global__ void __launch_bounds__(128, 4) qsim_kernel(
    const float* __restrict__ x,
    const float* __restrict__ in_W,
    const float* __restrict__ in_b,
    const float* __restrict__ gamma,
    const float* __restrict__ beta,
    const float* __restrict__ out_W,
    const float* __restrict__ out_b,
    float* __restrict__ out)
{
    const int tid  = threadIdx.x;
    const int lane = tid & 31;
    const int warp = tid >> 5;
    const int token = blockIdx.x * 4 + warp;
    const float* xrow = x + (size_t)token * DM;

    __shared__ float s_cx[NQ][128], s_sx[NQ][128];

    // ---------------- Stage 1: h = tanh(x @ in_W^T + b), LayerNorm ----------
    float acc[NQ];
    {
        float4 xv[4];
#pragma unroll
        for (int i = 0; i < 4; i++)
            xv[i] = *(const float4*)(xrow + lane * 4 + 128 * i);
#pragma unroll
        for (int q = 0; q < NQ; q++) {
            float a = 0.f;
#pragma unroll
            for (int i = 0; i < 4; i++) {
                float4 w = *(const float4*)(in_W + q * DM + lane * 4 + 128 * i);
                a = fmaf(xv[i].x, w.x, a); a = fmaf(xv[i].y, w.y, a);
                a = fmaf(xv[i].z, w.z, a); a = fmaf(xv[i].w, w.w, a);
            }
            acc[q] = warp_sum(a);
        }
    }
    float mu = 0.f;
#pragma unroll
    for (int q = 0; q < NQ; q++) {
        float t = acc[q] + __ldg(&in_b[q]);
        float e = __expf(2.f * t);
        acc[q] = 1.f - __fdividef(2.f, e + 1.f);   // tanh
        mu += acc[q];
    }
    mu *= 0.1f;
    float var = 0.f;
#pragma unroll
    for (int q = 0; q < NQ; q++) { float d = acc[q] - mu; var = fmaf(d, d, var); }
    var *= 0.1f;
    float rstd = rsqrtf(var + 1e-5f);
#pragma unroll
    for (int q = 0; q < NQ; q++) {
        float feat = fmaf((acc[q] - mu) * rstd, __ldg(&gamma[q]), __ldg(&beta[q]));
        float sn, cs;
        __sincosf(0.5f * feat, &sn, &cs);
        s_cx[q][tid] = cs; s_sx[q][tid] = sn;
    }

    // ---------------- Stage 2: 10-qubit statevector sim ---------------------
    // amp index = (lane << 5) | r, r = 2k + slot, qubit q <-> amp bit (9-q)
    // pr[k]/pi[k] pack amps (r=2k, r=2k+1) re/im as f32x2.
    u64 pr[16], pi[16];

    // --- Layer 0: |0..0> is a product state; build it by progressive doubling.
    // reg bits: slot=bit0 (q9), k bit b-1 = amp bit b (q = 9-b).
    {
        float m00r, m00i, m01r, m01i, m10r, m10i, m11r, m11i;
        // slot level (qubit 9)
        build_m(0, 9, s_cx[9][tid], s_sx[9][tid],
                m00r, m00i, m01r, m01i, m10r, m10i, m11r, m11i);
        pr[0] = pk2(m00r, m10r);
        pi[0] = pk2(m00i, m10i);
#pragma unroll
        for (int b = 1; b <= 4; b++) {
            const int qb = 9 - b;
            build_m(0, qb, s_cx[qb][tid], s_sx[qb][tid],
                    m00r, m00i, m01r, m01i, m10r, m10i, m11r, m11i);
            u64 C0r = bc2(m00r), C0i = bc2(m00i), C0in = bc2(-m00i);
            u64 C1r = bc2(m10r), C1i = bc2(m10i), C1in = bc2(-m10i);
            const int half = 1 << (b - 1);
#pragma unroll
            for (int k = 0; k < 8; k++) {
                if (k >= half) continue;
                u64 fr = pr[k], fi = pi[k];
                pr[k + half] = ffma2(C1in, fi, fmul2(C1r, fr));
                pi[k + half] = ffma2(C1i, fr, fmul2(C1r, fi));
                pr[k] = ffma2(C0in, fi, fmul2(C0r, fr));
                pi[k] = ffma2(C0i, fr, fmul2(C0r, fi));
            }
        }
        // lane factor over qubits 0..4 (lane bit 4-q)
        float lfr = 1.f, lfi = 0.f;
#pragma unroll
        for (int q = 0; q < 5; q++) {
            build_m(0, q, s_cx[q][tid], s_sx[q][tid],
                    m00r, m00i, m01r, m01i, m10r, m10i, m11r, m11i);
            int v = (lane >> (4 - q)) & 1;
            float gr = v ? m10r : m00r, gi = v ? m10i : m00i;
            float nr = lfr * gr - lfi * gi;
            float ni = lfr * gi + lfi * gr;
            lfr = nr; lfi = ni;
        }
        u64 LFr = bc2(lfr), LFi = bc2(lfi), LFin = bc2(-lfi);
#pragma unroll
        for (int k = 0; k < 16; k++) {
            u64 fr = pr[k], fi = pi[k];
            pr[k] = ffma2(LFin, fi, fmul2(LFr, fr));
            pi[k] = ffma2(LFi, fr, fmul2(LFr, fi));
        }
    }

#pragma unroll 1
    for (int l = 0; l < QL; l++) {
        if (l) {
            float m00r, m00i, m01r, m01i, m10r, m10i, m11r, m11i;
            // --- lane-bit gates: qubits 0..4, lane bit lb = 4-q ---
#pragma unroll
            for (int q = 0; q < 5; q++) {
                build_m(l, q, s_cx[q][tid], s_sx[q][tid],
                        m00r, m00i, m01r, m01i, m10r, m10i, m11r, m11i);
                const int lb = 4 - q;
                int v = (lane >> lb) & 1;
                float maar = v ? m11r : m00r, maai = v ? m11i : m00i;
                float mabr = v ? m10r : m01r, mabi = v ? m10i : m01i;
                u64 AAr = bc2(maar), AAi = bc2(maai), AAin = bc2(-maai);
                u64 ABr = bc2(mabr), ABi = bc2(mabi), ABin = bc2(-mabi);
#pragma unroll
                for (int k = 0; k < 16; k++) {
                    float a0, a1, b0, b1;
                    up2(pr[k], a0, a1); up2(pi[k], b0, b1);
                    float o0 = __shfl_xor_sync(FULL, a0, 1 << lb);
                    float o1 = __shfl_xor_sync(FULL, a1, 1 << lb);
                    float p0 = __shfl_xor_sync(FULL, b0, 1 << lb);
                    float p1 = __shfl_xor_sync(FULL, b1, 1 << lb);
                    u64 OTR = pk2(o0, o1), OTI = pk2(p0, p1);
                    u64 AR = pr[k], AI = pi[k];
                    u64 nr = ffma2(ABin, OTI, ffma2(ABr, OTR, ffma2(AAin, AI, fmul2(AAr, AR))));
                    u64 ni = ffma2(ABi, OTR, ffma2(ABr, OTI, ffma2(AAi, AR, fmul2(AAr, AI))));
                    pr[k] = nr; pi[k] = ni;
                }
            }
            // --- k-bit gates: qubits 5..8, k bit tk = 1<<(8-q) ---
#pragma unroll
            for (int q = 5; q < 9; q++) {
                build_m(l, q, s_cx[q][tid], s_sx[q][tid],
                        m00r, m00i, m01r, m01i, m10r, m10i, m11r, m11i);
                const int tk = 1 << (8 - q);
                u64 B00r = bc2(m00r), B00i = bc2(m00i), B00in = bc2(-m00i);
                u64 B01r = bc2(m01r), B01i = bc2(m01i), B01in = bc2(-m01i);
                u64 B10r = bc2(m10r), B10i = bc2(m10i), B10in = bc2(-m10i);
                u64 B11r = bc2(m11r), B11i = bc2(m11i), B11in = bc2(-m11i);
#pragma unroll
                for (int k = 0; k < 16; k++) {
                    if (k & tk) continue;
                    const int k2 = k | tk;
                    u64 p0r = pr[k], p0i = pi[k], p1r = pr[k2], p1i = pi[k2];
                    u64 n0r = ffma2(B01in, p1i, ffma2(B01r, p1r, ffma2(B00in, p0i, fmul2(B00r, p0r))));
                    u64 n0i = ffma2(B01i, p1r, ffma2(B01r, p1i, ffma2(B00i, p0r, fmul2(B00r, p0i))));
                    u64 n1r = ffma2(B11in, p1i, ffma2(B11r, p1r, ffma2(B10in, p0i, fmul2(B10r, p0r))));
                    u64 n1i = ffma2(B11i, p1r, ffma2(B11r, p1i, ffma2(B10i, p0r, fmul2(B10r, p0i))));
                    pr[k] = n0r; pi[k] = n0i; pr[k2] = n1r; pi[k2] = n1i;
                }
            }
            // --- slot gate: qubit 9 (amp bit 0, within-pack) ---
            {
                build_m(l, 9, s_cx[9][tid], s_sx[9][tid],
                        m00r, m00i, m01r, m01i, m10r, m10i, m11r, m11i);
                u64 C1 = pk2(m00r, m11r), C3 = pk2(m01r, m10r);
                u64 C2 = pk2(-m00i, -m11i), C4 = pk2(-m01i, -m10i);
                u64 E1 = pk2(m00i, m11i), E4 = pk2(m01i, m10i);
#pragma unroll
                for (int k = 0; k < 16; k++) {
                    u64 P = pr[k], Q = pi[k];
                    u64 SP = swap2(P), SQ = swap2(Q);
                    u64 nr = ffma2(C4, SQ, ffma2(C3, SP, ffma2(C2, Q, fmul2(C1, P))));
                    u64 ni = ffma2(E4, SP, ffma2(C3, SQ, ffma2(E1, P, fmul2(C1, Q))));
                    pr[k] = nr; pi[k] = ni;
                }
            }
        }

        // ---------------- CNOT chain ----------------
        // q=0..3 (all lane bits) compose to one lane permutation: src = lane ^ (lane>>1)
        {
            const int src = lane ^ (lane >> 1);
#pragma unroll
            for (int k = 0; k < 16; k++) {
                float a, b;
                up2(pr[k], a, b);
                a = __shfl_sync(FULL, a, src); b = __shfl_sync(FULL, b, src);
                pr[k] = pk2(a, b);
                up2(pi[k], a, b);
                a = __shfl_sync(FULL, a, src); b = __shfl_sync(FULL, b, src);
                pi[k] = pk2(a, b);
            }
        }
        // q=4: control lane bit0, target k bit3
        {
            const bool flip = (lane & 1);
#pragma unroll
            for (int k = 0; k < 8; k++) {
                u64 t = pr[k]; pr[k] = flip ? pr[k + 8] : t; pr[k + 8] = flip ? t : pr[k + 8];
                u64 u = pi[k]; pi[k] = flip ? pi[k + 8] : u; pi[k + 8] = flip ? u : pi[k + 8];
            }
        }
        // q=5..7: pure register swaps (free renames)
#pragma unroll
        for (int q = 5; q < 8; q++) {
            const int ck = 1 << (8 - q), tk2 = 1 << (7 - q);
#pragma unroll
            for (int k = 0; k < 16; k++) {
                if ((k & ck) && !(k & tk2)) {
                    const int k2 = k | tk2;
                    u64 t = pr[k]; pr[k] = pr[k2]; pr[k2] = t;
                    u64 u = pi[k]; pi[k] = pi[k2]; pi[k2] = u;
                }
            }
        }
        // q=8: control k bit0, target slot -> swap pack halves for odd k
#pragma unroll
        for (int k = 1; k < 16; k += 2) { pr[k] = swap2(pr[k]); pi[k] = swap2(pi[k]); }
        // q=9: control slot, target lane bit4 -> shuffle hi halves across xor 16
#pragma unroll
        for (int k = 0; k < 16; k++) {
            float a, b;
            up2(pr[k], a, b); b = __shfl_xor_sync(FULL, b, 16); pr[k] = pk2(a, b);
            up2(pi[k], a, b); b = __shfl_xor_sync(FULL, b, 16); pi[k] = pk2(a, b);
        }
    }

    // ---------------- Stage 3: measurement + output projection --------------
    u64 totP = 0, sbP0 = 0, sbP1 = 0, sbP2 = 0, sbP3 = 0;
#pragma unroll
    for (int k = 0; k < 16; k++) {
        u64 t = fmul2(pr[k], pr[k]);
        t = ffma2(pi[k], pi[k], t);
        totP = fadd2(totP, t);
        if (!(k & 1)) sbP0 = fadd2(sbP0, t);
        if (!(k & 2)) sbP1 = fadd2(sbP1, t);
        if (!(k & 4)) sbP2 = fadd2(sbP2, t);
        if (!(k & 8)) sbP3 = fadd2(sbP3, t);
    }
    float z[NQ];
    float t0, t1;
    up2(totP, t0, t1);
    float tot = t0 + t1;
    z[9] = warp_sum(t0 - t1);
    {
        float u0, u1;
        up2(sbP0, u0, u1); z[8] = warp_sum(2.f * (u0 + u1) - tot);
        up2(sbP1, u0, u1); z[7] = warp_sum(2.f * (u0 + u1) - tot);
        up2(sbP2, u0, u1); z[6] = warp_sum(2.f * (u0 + u1) - tot);
        up2(sbP3, u0, u1); z[5] = warp_sum(2.f * (u0 + u1) - tot);
    }
#pragma unroll
    for (int q = 0; q < 5; q++) {
        const int lb = 4 - q;
        float v = ((lane >> lb) & 1) ? -tot : tot;
        z[q] = warp_sum(v);
    }

    // out = x + q_out @ out_W^T + out_b
    u64 zP[5];
#pragma unroll
    for (int j = 0; j < 5; j++) zP[j] = pk2(z[2 * j], z[2 * j + 1]);

    float* outr = out + (size_t)token * DM;
#pragma unroll
    for (int i = 0; i < 4; i++) {
        const int dbase = lane * 4 + 128 * i;
        float4 xv = *(const float4*)(xrow + dbase);
        float4 ob = *(const float4*)(out_b + dbase);
        float res[4];
#pragma unroll
        for (int c = 0; c < 4; c++) {
            const u64* wrow = (const u64*)(out_W + (dbase + c) * NQ);
            u64 a2 = fmul2(zP[0], wrow[0]);
            a2 = ffma2(zP[1], wrow[1], a2);
            a2 = ffma2(zP[2], wrow[2], a2);
            a2 = ffma2(zP[3], wrow[3], a2);
            a2 = ffma2(zP[4], wrow[4], a2);
            float s0, s1; up2(a2, s0, s1);
            res[c] = s0 + s1;
        }
        float4 o;
        o.x = xv.x + ob.x + res[0];
        o.y = xv.y + ob.y + res[1];
        o.z = xv.z + ob.z + res[2];
        o.w = xv.w + ob.w + res[3];
        *(float4*)(outr + dbase) = o;
    }
}

extern "C" void kernel_launch(void* const* d_in, const int* in_sizes, int n_in,
                              void* d_out, int out_size) {
    const float* x       = (const float*)d_in[0];
    const float* in_W    = (const float*)d_in[1];
    const float* in_b    = (const float*)d_in[2];
    const float* gamma   = (const float*)d_in[3];
    const float* beta    = (const float*)d_in[4];
    const float* weights = (const float*)d_in[5];
    const float* out_W   = (const float*)d_in[6];
    const float* out_b   = (const float*)d_in[7];
    float* out = (float*)d_out;

    prep_kernel<<<1, 64>>>(weights);
    qsim_kernel<<<NTOK / 4, 128>>>(x, in_W, in_b, gamma, beta, out_W, out_b, out);
}

// round 5
// speedup vs baseline: 1.6792x; 1.0055x over previous
#include <cuda_runtime.h>

typedef unsigned long long u64;
#define FULL 0xffffffffu
#define NQ 10
#define QL 4
#define DM 512
#define NTOK (8*2048)

// Precomputed weight-gate packs per (layer,qubit):
// [0..3] = W00,W01,W10,W11 as (re,im) packs
// [4] = i*W00 + i*W01, [5] = i*W01 - i*W00, [6] = i*W10 + i*W11, [7] = i*W11 - i*W10
__device__ u64 g_WP[QL * NQ * 8];

__device__ __forceinline__ u64 pk2(float lo, float hi) {
    u64 r; asm("mov.b64 %0,{%1,%2};" : "=l"(r) : "f"(lo), "f"(hi)); return r;
}
__device__ __forceinline__ void up2(u64 v, float& lo, float& hi) {
    asm("mov.b64 {%0,%1},%2;" : "=f"(lo), "=f"(hi) : "l"(v));
}
__device__ __forceinline__ u64 bc2(float v) { return pk2(v, v); }
__device__ __forceinline__ u64 ffma2(u64 a, u64 b, u64 c) {
    u64 d; asm("fma.rn.f32x2 %0,%1,%2,%3;" : "=l"(d) : "l"(a), "l"(b), "l"(c)); return d;
}
__device__ __forceinline__ u64 fmul2(u64 a, u64 b) {
    u64 d; asm("mul.rn.f32x2 %0,%1,%2;" : "=l"(d) : "l"(a), "l"(b)); return d;
}
__device__ __forceinline__ u64 fadd2(u64 a, u64 b) {
    u64 d; asm("add.rn.f32x2 %0,%1,%2;" : "=l"(d) : "l"(a), "l"(b)); return d;
}
__device__ __forceinline__ u64 swap2(u64 v) { float lo, hi; up2(v, lo, hi); return pk2(hi, lo); }

__global__ void prep_kernel(const float* __restrict__ weights) {
    int t = threadIdx.x;
    if (t < QL * NQ) {
        float ty = 0.5f * weights[t * 2 + 0];
        float tz = 0.5f * weights[t * 2 + 1];
        float sy, cy, sz, cz;
        sincosf(ty, &sy, &cy);
        sincosf(tz, &sz, &cz);
        // W = RZw * RY
        float w00r =  cz * cy, w00i = -sz * cy;
        float w01r = -cz * sy, w01i =  sz * sy;
        float w10r =  cz * sy, w10i =  sz * sy;
        float w11r =  cz * cy, w11i =  sz * cy;
        u64* o = &g_WP[t * 8];
        o[0] = pk2(w00r, w00i);
        o[1] = pk2(w01r, w01i);
        o[2] = pk2(w10r, w10i);
        o[3] = pk2(w11r, w11i);
        // i*w = (-wi, wr)
        o[4] = pk2(-w00i - w01i, w00r + w01r);   // S0 = iW00 + iW01
        o[5] = pk2( w00i - w01i, w01r - w00r);   // D0 = iW01 - iW00
        o[6] = pk2(-w10i - w11i, w10r + w11r);   // S1 = iW10 + iW11
        o[7] = pk2( w10i - w11i, w11r - w10r);   // D1 = iW11 - iW10
    }
}

__device__ __forceinline__ float warp_sum(float v) {
#pragma unroll
    for (int o = 16; o; o >>= 1) v += __shfl_xor_sync(FULL, v, o);
    return v;
}

// Fused gate matrix M = W * (RZt * RX), with A = RZt*RX:
// a00=(cc,-sc) a01=(-ss,-sc) a10=(ss,-sc) a11=(cc,sc)
__device__ __forceinline__ void build_m(int l, int q, float c, float s,
    float& m00r, float& m00i, float& m01r, float& m01i,
    float& m10r, float& m10i, float& m11r, float& m11i)
{
    const u64* w = &g_WP[(l * NQ + q) * 8];
    u64 W00 = w[0], W01 = w[1], W10 = w[2], W11 = w[3];
    u64 S0 = w[4], D0 = w[5], S1 = w[6], D1 = w[7];
    float cc = c * c, ss = s * s, sc = s * c;
    u64 CC = bc2(cc), SS = bc2(ss), NSS = bc2(-ss), SC = bc2(sc), NSC = bc2(-sc);
    u64 M00 = ffma2(SS, W01, ffma2(NSC, S0, fmul2(CC, W00)));
    u64 M01 = ffma2(NSS, W00, ffma2(SC, D0, fmul2(CC, W01)));
    u64 M10 = ffma2(SS, W11, ffma2(NSC, S1, fmul2(CC, W10)));
    u64 M11 = ffma2(NSS, W10, ffma2(SC, D1, fmul2(CC, W11)));
    up2(M00, m00r, m00i); up2(M01, m01r, m01i);
    up2(M10, m10r, m10i); up2(M11, m11r, m11i);
}

__global__ void __launch_bounds__(128, 4) qsim_kernel(
    const float* __restrict__ x,
    const float* __restrict__ in_W,
    const float* __restrict__ in_b,
    const float* __restrict__ gamma,
    const float* __restrict__ beta,
    const float* __restrict__ out_W,
    const float* __restrict__ out_b,
    float* __restrict__ out)
{
    const int tid  = threadIdx.x;
    const int lane = tid & 31;
    const int warp = tid >> 5;
    const int token = blockIdx.x * 4 + warp;
    const float* xrow = x + (size_t)token * DM;

    __shared__ float s_cx[NQ][128], s_sx[NQ][128];

    // ---------------- Stage 1: h = tanh(x @ in_W^T + b), LayerNorm ----------
    float acc[NQ];
    {
        float4 xv[4];
#pragma unroll
        for (int i = 0; i < 4; i++)
            xv[i] = *(const float4*)(xrow + lane * 4 + 128 * i);
#pragma unroll
        for (int q = 0; q < NQ; q++) {
            float a = 0.f;
#pragma unroll
            for (int i = 0; i < 4; i++) {
                float4 w = *(const float4*)(in_W + q * DM + lane * 4 + 128 * i);
                a = fmaf(xv[i].x, w.x, a); a = fmaf(xv[i].y, w.y, a);
                a = fmaf(xv[i].z, w.z, a); a = fmaf(xv[i].w, w.w, a);
            }
            acc[q] = warp_sum(a);
        }
    }
    float mu = 0.f;
#pragma unroll
    for (int q = 0; q < NQ; q++) {
        float t = acc[q] + __ldg(&in_b[q]);
        float e = __expf(2.f * t);
        acc[q] = 1.f - __fdividef(2.f, e + 1.f);   // tanh
        mu += acc[q];
    }
    mu *= 0.1f;
    float var = 0.f;
#pragma unroll
    for (int q = 0; q < NQ; q++) { float d = acc[q] - mu; var = fmaf(d, d, var); }
    var *= 0.1f;
    float rstd = rsqrtf(var + 1e-5f);
#pragma unroll
    for (int q = 0; q < NQ; q++) {
        float feat = fmaf((acc[q] - mu) * rstd, __ldg(&gamma[q]), __ldg(&beta[q]));
        float sn, cs;
        __sincosf(0.5f * feat, &sn, &cs);
        s_cx[q][tid] = cs; s_sx[q][tid] = sn;
    }

    // ---------------- Stage 2: 10-qubit statevector sim ---------------------
    // amp index = (vlane << 5) | r, r = 2k + slot, qubit q <-> amp bit (9-q)
    // pr[k]/pi[k] pack amps (r=2k, r=2k+1) re/im as f32x2.
    // Lane relabeling: the fused 4-CNOT lane permutation sigma(l)=l^(l>>1) is
    // GF(2)-linear; we never move data. After L skipped perms, physical lane p
    // holds virtual lane sigma^{-L}(p); a virtual-bit-lb exchange uses physical
    // xor-mask sigma^L(1<<lb).
    u64 pr[16], pi[16];

    // --- Layer 0: |0..0> is a product state; build it by progressive doubling.
    {
        float m00r, m00i, m01r, m01i, m10r, m10i, m11r, m11i;
        // slot level (qubit 9)
        build_m(0, 9, s_cx[9][tid], s_sx[9][tid],
                m00r, m00i, m01r, m01i, m10r, m10i, m11r, m11i);
        pr[0] = pk2(m00r, m10r);
        pi[0] = pk2(m00i, m10i);
#pragma unroll
        for (int b = 1; b <= 4; b++) {
            const int qb = 9 - b;
            build_m(0, qb, s_cx[qb][tid], s_sx[qb][tid],
                    m00r, m00i, m01r, m01i, m10r, m10i, m11r, m11i);
            u64 C0r = bc2(m00r), C0i = bc2(m00i), C0in = bc2(-m00i);
            u64 C1r = bc2(m10r), C1i = bc2(m10i), C1in = bc2(-m10i);
            const int half = 1 << (b - 1);
#pragma unroll
            for (int k = 0; k < 8; k++) {
                if (k >= half) continue;
                u64 fr = pr[k], fi = pi[k];
                pr[k + half] = ffma2(C1in, fi, fmul2(C1r, fr));
                pi[k + half] = ffma2(C1i, fr, fmul2(C1r, fi));
                pr[k] = ffma2(C0in, fi, fmul2(C0r, fr));
                pi[k] = ffma2(C0i, fr, fmul2(C0r, fi));
            }
        }
        // lane factor over qubits 0..4 (lane bit 4-q)
        float lfr = 1.f, lfi = 0.f;
#pragma unroll
        for (int q = 0; q < 5; q++) {
            build_m(0, q, s_cx[q][tid], s_sx[q][tid],
                    m00r, m00i, m01r, m01i, m10r, m10i, m11r, m11i);
            int v = (lane >> (4 - q)) & 1;
            float gr = v ? m10r : m00r, gi = v ? m10i : m00i;
            float nr = lfr * gr - lfi * gi;
            float ni = lfr * gi + lfi * gr;
            lfr = nr; lfi = ni;
        }
        u64 LFr = bc2(lfr), LFi = bc2(lfi), LFin = bc2(-lfi);
#pragma unroll
        for (int k = 0; k < 16; k++) {
            u64 fr = pr[k], fi = pi[k];
            pr[k] = ffma2(LFin, fi, fmul2(LFr, fr));
            pi[k] = ffma2(LFi, fr, fmul2(LFr, fi));
        }
    }

    // relabel state: vlane = sigma^{-L}(lane); m0..m4 = sigma^L(1<<b)
    int vlane = lane;
    int m0 = 1, m1 = 2, m2 = 4, m3 = 8, m4 = 16;

#pragma unroll 1
    for (int l = 0; l < QL; l++) {
        if (l) {
            float m00r, m00i, m01r, m01i, m10r, m10i, m11r, m11i;
            // --- lane-bit gates: qubits 0..4, virtual lane bit lb = 4-q ---
#pragma unroll
            for (int q = 0; q < 5; q++) {
                build_m(l, q, s_cx[q][tid], s_sx[q][tid],
                        m00r, m00i, m01r, m01i, m10r, m10i, m11r, m11i);
                const int lb = 4 - q;
                const int msk = (lb == 4) ? m4 : (lb == 3) ? m3 : (lb == 2) ? m2
                              : (lb == 1) ? m1 : m0;
                int v = (vlane >> lb) & 1;
                float maar = v ? m11r : m00r, maai = v ? m11i : m00i;
                float mabr = v ? m10r : m01r, mabi = v ? m10i : m01i;
                u64 AAr = bc2(maar), AAi = bc2(maai), AAin = bc2(-maai);
                u64 ABr = bc2(mabr), ABi = bc2(mabi), ABin = bc2(-mabi);
#pragma unroll
                for (int k = 0; k < 16; k++) {
                    float a0, a1, b0, b1;
                    up2(pr[k], a0, a1); up2(pi[k], b0, b1);
                    float o0 = __shfl_xor_sync(FULL, a0, msk);
                    float o1 = __shfl_xor_sync(FULL, a1, msk);
                    float p0 = __shfl_xor_sync(FULL, b0, msk);
                    float p1 = __shfl_xor_sync(FULL, b1, msk);
                    u64 OTR = pk2(o0, o1), OTI = pk2(p0, p1);
                    u64 AR = pr[k], AI = pi[k];
                    u64 nr = ffma2(ABin, OTI, ffma2(ABr, OTR, ffma2(AAin, AI, fmul2(AAr, AR))));
                    u64 ni = ffma2(ABi, OTR, ffma2(ABr, OTI, ffma2(AAi, AR, fmul2(AAr, AI))));
                    pr[k] = nr; pi[k] = ni;
                }
            }
            // --- k-bit gates: qubits 5..8, k bit tk = 1<<(8-q) ---
#pragma unroll
            for (int q = 5; q < 9; q++) {
                build_m(l, q, s_cx[q][tid], s_sx[q][tid],
                        m00r, m00i, m01r, m01i, m10r, m10i, m11r, m11i);
                const int tk = 1 << (8 - q);
                u64 B00r = bc2(m00r), B00i = bc2(m00i), B00in = bc2(-m00i);
                u64 B01r = bc2(m01r), B01i = bc2(m01i), B01in = bc2(-m01i);
                u64 B10r = bc2(m10r), B10i = bc2(m10i), B10in = bc2(-m10i);
                u64 B11r = bc2(m11r), B11i = bc2(m11i), B11in = bc2(-m11i);
#pragma unroll
                for (int k = 0; k < 16; k++) {
                    if (k & tk) continue;
                    const int k2 = k | tk;
                    u64 p0r = pr[k], p0i = pi[k], p1r = pr[k2], p1i = pi[k2];
                    u64 n0r = ffma2(B01in, p1i, ffma2(B01r, p1r, ffma2(B00in, p0i, fmul2(B00r, p0r))));
                    u64 n0i = ffma2(B01i, p1r, ffma2(B01r, p1i, ffma2(B00i, p0r, fmul2(B00r, p0i))));
                    u64 n1r = ffma2(B11in, p1i, ffma2(B11r, p1r, ffma2(B10in, p0i, fmul2(B10r, p0r))));
                    u64 n1i = ffma2(B11i, p1r, ffma2(B11r, p1i, ffma2(B10i, p0r, fmul2(B10r, p0i))));
                    pr[k] = n0r; pi[k] = n0i; pr[k2] = n1r; pi[k2] = n1i;
                }
            }
            // --- slot gate: qubit 9 (amp bit 0, within-pack) ---
            {
                build_m(l, 9, s_cx[9][tid], s_sx[9][tid],
                        m00r, m00i, m01r, m01i, m10r, m10i, m11r, m11i);
                u64 C1 = pk2(m00r, m11r), C3 = pk2(m01r, m10r);
                u64 C2 = pk2(-m00i, -m11i), C4 = pk2(-m01i, -m10i);
                u64 E1 = pk2(m00i, m11i), E4 = pk2(m01i, m10i);
#pragma unroll
                for (int k = 0; k < 16; k++) {
                    u64 P = pr[k], Q = pi[k];
                    u64 SP = swap2(P), SQ = swap2(Q);
                    u64 nr = ffma2(C4, SQ, ffma2(C3, SP, ffma2(C2, Q, fmul2(C1, P))));
                    u64 ni = ffma2(E4, SP, ffma2(C3, SQ, ffma2(E1, P, fmul2(C1, Q))));
                    pr[k] = nr; pi[k] = ni;
                }
            }
        }

        // ---------------- CNOT chain (layers 0..2; layer 3 absorbed) --------
        if (l < 3) {
            // q=0..3 lane perm: SKIPPED -> advance the relabeling instead
            vlane = vlane ^ (vlane >> 1) ^ (vlane >> 2) ^ (vlane >> 3) ^ (vlane >> 4);
            m0 ^= m0 >> 1; m1 ^= m1 >> 1; m2 ^= m2 >> 1; m3 ^= m3 >> 1; m4 ^= m4 >> 1;
            // q=4: control virtual lane bit0, target k bit3
            {
                const bool flip = (vlane & 1);
#pragma unroll
                for (int k = 0; k < 8; k++) {
                    u64 t = pr[k]; pr[k] = flip ? pr[k + 8] : t; pr[k + 8] = flip ? t : pr[k + 8];
                    u64 u = pi[k]; pi[k] = flip ? pi[k + 8] : u; pi[k + 8] = flip ? u : pi[k + 8];
                }
            }
            // q=5..7: pure register swaps (free renames)
#pragma unroll
            for (int q = 5; q < 8; q++) {
                const int ck = 1 << (8 - q), tk2 = 1 << (7 - q);
#pragma unroll
                for (int k = 0; k < 16; k++) {
                    if ((k & ck) && !(k & tk2)) {
                        const int k2 = k | tk2;
                        u64 t = pr[k]; pr[k] = pr[k2]; pr[k2] = t;
                        u64 u = pi[k]; pi[k] = pi[k2]; pi[k2] = u;
                    }
                }
            }
            // q=8: control k bit0, target slot -> swap pack halves for odd k
#pragma unroll
            for (int k = 1; k < 16; k += 2) { pr[k] = swap2(pr[k]); pi[k] = swap2(pi[k]); }
            // q=9: control slot, target virtual lane bit4 -> shuffle hi halves across m4
#pragma unroll
            for (int k = 0; k < 16; k++) {
                float a, b;
                up2(pr[k], a, b); b = __shfl_xor_sync(FULL, b, m4); pr[k] = pk2(a, b);
                up2(pi[k], a, b); b = __shfl_xor_sync(FULL, b, m4); pi[k] = pk2(a, b);
            }
        }
    }

    // ---------------- Stage 3: measurement (final CNOT chain absorbed) ------
    // Final chain is GF(2)-linear on the amp index: post bit B'(q)=9-q maps to
    //   B'=0..8: parity(orig bits B'..9);  B'=9: parity(orig bits 0..8).
    // orig bits: slot = bit0, k = bits1..4, vlane = bits5..9 (virtual!).
    const u64 SGN = 0x8000000080000000ULL;
    u64 AT = 0, A1 = 0, A2 = 0, A3 = 0, A4 = 0;
#pragma unroll
    for (int k = 0; k < 16; k++) {
        u64 P = ffma2(pi[k], pi[k], fmul2(pr[k], pr[k]));
        u64 NP = P ^ SGN;
        const int k3 = (k >> 3) & 1, k2b = (k >> 2) & 1, k1 = (k >> 1) & 1, k0 = k & 1;
        AT = fadd2(AT, P);
        A1 = fadd2(A1, k3 ? NP : P);
        A2 = fadd2(A2, (k3 ^ k2b) ? NP : P);
        A3 = fadd2(A3, (k3 ^ k2b ^ k1) ? NP : P);
        A4 = fadd2(A4, (k3 ^ k2b ^ k1 ^ k0) ? NP : P);
    }
    float lo, hi;
    up2(AT, lo, hi); const float T  = lo + hi;
    up2(A1, lo, hi); const float U1 = lo + hi;
    up2(A2, lo, hi); const float U2 = lo + hi;
    up2(A3, lo, hi); const float U3 = lo + hi;
    up2(A4, lo, hi); const float U4 = lo + hi, Dp = lo - hi;

    const int pl  = __popc(vlane) & 1;
    const int pl4 = __popc(vlane & 15) & 1;
    float z[NQ];
    z[0] = warp_sum(pl4 ? -Dp : Dp);
    z[1] = warp_sum((__popc(vlane >> 3) & 1) ? -T : T);
    z[2] = warp_sum((__popc(vlane >> 2) & 1) ? -T : T);
    z[3] = warp_sum((__popc(vlane >> 1) & 1) ? -T : T);
    z[4] = warp_sum(pl ? -T : T);
    z[5] = warp_sum(pl ? -U1 : U1);
    z[6] = warp_sum(pl ? -U2 : U2);
    z[7] = warp_sum(pl ? -U3 : U3);
    z[8] = warp_sum(pl ? -U4 : U4);
    z[9] = warp_sum(pl ? -Dp : Dp);

    // out = x + q_out @ out_W^T + out_b
    u64 zP[5];
#pragma unroll
    for (int j = 0; j < 5; j++) zP[j] = pk2(z[2 * j], z[2 * j + 1]);

    float* outr = out + (size_t)token * DM;
#pragma unroll
    for (int i = 0; i < 4; i++) {
        const int dbase = lane * 4 + 128 * i;
        float4 xv = *(const float4*)(xrow + dbase);
        float4 ob = *(const float4*)(out_b + dbase);
        float res[4];
#pragma unroll
        for (int c = 0; c < 4; c++) {
            const u64* wrow = (const u64*)(out_W + (dbase + c) * NQ);
            u64 a2 = fmul2(zP[0], wrow[0]);
            a2 = ffma2(zP[1], wrow[1], a2);
            a2 = ffma2(zP[2], wrow[2], a2);
            a2 = ffma2(zP[3], wrow[3], a2);
            a2 = ffma2(zP[4], wrow[4], a2);
            float s0, s1; up2(a2, s0, s1);
            res[c] = s0 + s1;
        }
        float4 o;
        o.x = xv.x + ob.x + res[0];
        o.y = xv.y + ob.y + res[1];
        o.z = xv.z + ob.z + res[2];
        o.w = xv.w + ob.w + res[3];
        *(float4*)(outr + dbase) = o;
    }
}

extern "C" void kernel_launch(void* const* d_in, const int* in_sizes, int n_in,
                              void* d_out, int out_size) {
    const float* x       = (const float*)d_in[0];
    const float* in_W    = (const float*)d_in[1];
    const float* in_b    = (const float*)d_in[2];
    const float* gamma   = (const float*)d_in[3];
    const float* beta    = (const float*)d_in[4];
    const float* weights = (const float*)d_in[5];
    const float* out_W   = (const float*)d_in[6];
    const float* out_b   = (const float*)d_in[7];
    float* out = (float*)d_out;

    prep_kernel<<<1, 64>>>(weights);
    qsim_kernel<<<NTOK / 4, 128>>>(x, in_W, in_b, gamma, beta, out_W, out_b, out);
}